// round 11
// baseline (speedup 1.0000x reference)
#include <cuda_runtime.h>
#include <cuda_fp16.h>
#include <math.h>
#include <stdint.h>

#define EPS 1e-5f
#define MAX_NORM 0.95f
#define D 128
#define MAXN 50000
#define MAXNP 50048   // padded to multiple of 128 (tile loads run unguarded)
#define MAXE 800000
#define MAXL 2

// ---------------- scratch (static device globals) ---------------------------
__device__ __half g_t16[MAXNP * D];        // fp16 message tangents (gather source)
__device__ __half g_a0hi[MAXNP * D];       // GEMM input buffer 0 (hi)
__device__ __half g_a0lo[MAXNP * D];       // GEMM input buffer 0 (lo)
__device__ __half g_a1hi[MAXNP * D];       // GEMM input buffer 1 (hi)
__device__ __half g_a1lo[MAXNP * D];       // GEMM input buffer 1 (lo)
__device__ __half g_whi[2 * MAXL * D * D]; // pre-split weights hi (msg block, then upd block)
__device__ __half g_wlo[2 * MAXL * D * D]; // pre-split weights lo
__device__ int    g_deg[MAXN];
__device__ int    g_off[MAXN + 1];
__device__ int    g_cur[MAXN];
__device__ int    g_csrc[MAXE];

// ---------------- scalar chains ---------------------------------------------
__device__ __forceinline__ float s_log0(float n) {
    float nm  = fmaxf(n, EPS);
    float arg = fminf(nm, 1.0f - EPS);
    return atanhf(arg) / nm;
}
__device__ __forceinline__ float chain_epl(float n) {
    float nm = fmaxf(n, EPS);
    float a  = tanhf(nm) / nm;
    float na = n * a;
    float b  = (na > MAX_NORM) ? MAX_NORM / fmaxf(na, EPS) : 1.0f;
    float nb = na * b;
    float nbm = fmaxf(nb, EPS);
    float arg = fminf(nbm, 1.0f - EPS);
    float c  = atanhf(arg) / nbm;
    return a * b * c;
}
__device__ __forceinline__ float chain_ep(float n) {
    float nm = fmaxf(n, EPS);
    float a  = tanhf(nm) / nm;
    float na = n * a;
    float b  = (na > MAX_NORM) ? MAX_NORM / fmaxf(na, EPS) : 1.0f;
    return a * b;
}

// ---------------- fp16 mma helper -------------------------------------------
__device__ __forceinline__ void mma_f16(float* d, uint32_t a0, uint32_t a1,
                                        uint32_t a2, uint32_t a3,
                                        uint32_t b0, uint32_t b1) {
    asm volatile(
        "mma.sync.aligned.m16n8k16.row.col.f32.f16.f16.f32 "
        "{%0,%1,%2,%3}, {%4,%5,%6,%7}, {%8,%9}, {%0,%1,%2,%3};\n"
        : "+f"(d[0]), "+f"(d[1]), "+f"(d[2]), "+f"(d[3])
        : "r"(a0), "r"(a1), "r"(a2), "r"(a3), "r"(b0), "r"(b1));
}
// split float pair into fp16 hi + fp16 residual lo (packed half2 words)
__device__ __forceinline__ void split2(float x, float y, uint32_t& hi, uint32_t& lo) {
    __half2 h = __floats2half2_rn(x, y);
    float2 hf = __half22float2(h);
    __half2 l = __floats2half2_rn(x - hf.x, y - hf.y);
    hi = *reinterpret_cast<uint32_t*>(&h);
    lo = *reinterpret_cast<uint32_t*>(&l);
}

// ---------------- weight pre-split -------------------------------------------
__global__ void wsplit_kernel(const float* __restrict__ W,
                              __half* __restrict__ hi, __half* __restrict__ lo, int n2) {
    int i = blockIdx.x * blockDim.x + threadIdx.x;
    if (i < n2) {
        float2 v = reinterpret_cast<const float2*>(W)[i];
        uint32_t h, l;
        split2(v.x, v.y, h, l);
        reinterpret_cast<uint32_t*>(hi)[i] = h;
        reinterpret_cast<uint32_t*>(lo)[i] = l;
    }
}

// ---------------- CSR construction ------------------------------------------
__global__ void zero_int_kernel(int* __restrict__ p, int n) {
    int i = blockIdx.x * blockDim.x + threadIdx.x;
    if (i < n) p[i] = 0;
}
__global__ void hist_kernel(const int* __restrict__ dst, int E) {
    int e = blockIdx.x * blockDim.x + threadIdx.x;
    if (e < E) atomicAdd(&g_deg[dst[e]], 1);
}
__global__ void scan_kernel(int N) {
    int lane = threadIdx.x & 31, wid = threadIdx.x >> 5;
    __shared__ int wsum[32];
    __shared__ int running;
    if (threadIdx.x == 0) running = 0;
    __syncthreads();
    for (int base = 0; base < N; base += 1024) {
        int i = base + (int)threadIdx.x;
        int v = (i < N) ? g_deg[i] : 0;
        int x = v;
#pragma unroll
        for (int o = 1; o < 32; o <<= 1) {
            int y = __shfl_up_sync(0xffffffffu, x, o);
            if (lane >= o) x += y;
        }
        if (lane == 31) wsum[wid] = x;
        __syncthreads();
        if (wid == 0) {
            int s = wsum[lane];
#pragma unroll
            for (int o = 1; o < 32; o <<= 1) {
                int y = __shfl_up_sync(0xffffffffu, s, o);
                if (lane >= o) s += y;
            }
            wsum[lane] = s;
        }
        __syncthreads();
        int warp_prefix = (wid == 0) ? 0 : wsum[wid - 1];
        int excl = running + warp_prefix + (x - v);
        if (i < N) { g_off[i] = excl; g_cur[i] = excl; }
        int tile_total = wsum[31];
        __syncthreads();
        if (threadIdx.x == 0) running += tile_total;
        __syncthreads();
    }
    if (threadIdx.x == 0) g_off[N] = running;
}
__global__ void fill_kernel(const int* __restrict__ src, const int* __restrict__ dst, int E) {
    int e = blockIdx.x * blockDim.x + threadIdx.x;
    if (e < E) {
        int p = atomicAdd(&g_cur[dst[e]], 1);
        g_csrc[p] = src[e];
    }
}

// ---------------- prep: (vhi,vlo) = split(log0(x)) ---------------------------
__global__ void prep_log0_kernel(const float* __restrict__ in,
                                 __half* __restrict__ ohi, __half* __restrict__ olo, int N) {
    int w    = (blockIdx.x * blockDim.x + threadIdx.x) >> 5;
    int lane = threadIdx.x & 31;
    if (w >= N) return;
    float4 v = *reinterpret_cast<const float4*>(&in[(size_t)w * D + lane * 4]);
    float p = v.x * v.x + v.y * v.y + v.z * v.z + v.w * v.w;
#pragma unroll
    for (int off = 16; off; off >>= 1) p += __shfl_xor_sync(0xffffffffu, p, off);
    float s = s_log0(sqrtf(p));
    uint32_t h0, l0, h1, l1;
    split2(v.x * s, v.y * s, h0, l0);
    split2(v.z * s, v.w * s, h1, l1);
    size_t o = (size_t)w * D + lane * 4;
    *reinterpret_cast<uint2*>(&ohi[o]) = make_uint2(h0, h1);
    *reinterpret_cast<uint2*>(&olo[o]) = make_uint2(l0, l1);
}

// ---------------- fused gather(fp16) + mean + chain_epl + split -------------
__global__ void agg_kernel(__half* __restrict__ ohi, __half* __restrict__ olo, int N) {
    int w    = (blockIdx.x * blockDim.x + threadIdx.x) >> 5;
    int lane = threadIdx.x & 31;
    if (w >= N) return;
    int beg = g_off[w], end = g_off[w + 1];
    float ax = 0.f, ay = 0.f, az = 0.f, aw = 0.f;
    int e = beg;
    int col = lane * 4;
#pragma unroll 1
    for (; e + 4 <= end; e += 4) {
        int s0 = g_csrc[e], s1 = g_csrc[e + 1], s2 = g_csrc[e + 2], s3 = g_csrc[e + 3];
        uint2 u0 = *reinterpret_cast<const uint2*>(&g_t16[(size_t)s0 * D + col]);
        uint2 u1 = *reinterpret_cast<const uint2*>(&g_t16[(size_t)s1 * D + col]);
        uint2 u2 = *reinterpret_cast<const uint2*>(&g_t16[(size_t)s2 * D + col]);
        uint2 u3 = *reinterpret_cast<const uint2*>(&g_t16[(size_t)s3 * D + col]);
        float2 a, b;
        a = __half22float2(*(__half2*)&u0.x); b = __half22float2(*(__half2*)&u0.y);
        ax += a.x; ay += a.y; az += b.x; aw += b.y;
        a = __half22float2(*(__half2*)&u1.x); b = __half22float2(*(__half2*)&u1.y);
        ax += a.x; ay += a.y; az += b.x; aw += b.y;
        a = __half22float2(*(__half2*)&u2.x); b = __half22float2(*(__half2*)&u2.y);
        ax += a.x; ay += a.y; az += b.x; aw += b.y;
        a = __half22float2(*(__half2*)&u3.x); b = __half22float2(*(__half2*)&u3.y);
        ax += a.x; ay += a.y; az += b.x; aw += b.y;
    }
    for (; e < end; e++) {
        int s0 = g_csrc[e];
        uint2 u0 = *reinterpret_cast<const uint2*>(&g_t16[(size_t)s0 * D + col]);
        float2 a = __half22float2(*(__half2*)&u0.x);
        float2 b = __half22float2(*(__half2*)&u0.y);
        ax += a.x; ay += a.y; az += b.x; aw += b.y;
    }
    float inv = 1.0f / fmaxf((float)(end - beg), 1.0f);
    ax *= inv; ay *= inv; az *= inv; aw *= inv;
    float p = ax * ax + ay * ay + az * az + aw * aw;
#pragma unroll
    for (int off = 16; off; off >>= 1) p += __shfl_xor_sync(0xffffffffu, p, off);
    float s = chain_epl(sqrtf(p));
    uint32_t h0, l0, h1, l1;
    split2(ax * s, ay * s, h0, l0);
    split2(az * s, aw * s, h1, l1);
    size_t o = (size_t)w * D + col;
    *reinterpret_cast<uint2*>(&ohi[o]) = make_uint2(h0, h1);
    *reinterpret_cast<uint2*>(&olo[o]) = make_uint2(l0, l1);
}

// ---------------- 3x fp16-split tensor-core GEMM + hyperbolic epilogue ------
// CTA: 128x128 output tile, K=128 resident. 16 warps, warp tile 32x32.
// Inputs pre-split: prologue is pure uint4 copy (zero CVTs).
// mode 0: chain_epl, fp16 store to out16 (message tangents)
// mode 1: chain_ep,  fp32 store to out   (final output)
// mode 2: chain_epl, split store to outhi/outlo (next-layer tangent)
#define STR 68   // half2-word row stride: 68 mod 32 == 4 -> banks 4g+c, conflict-free

__global__ __launch_bounds__(512) void gemm_hyp_tc_kernel(
    const __half* __restrict__ Ahi_g, const __half* __restrict__ Alo_g,
    const __half* __restrict__ Whi_g, const __half* __restrict__ Wlo_g,
    const float* __restrict__ bias, float* __restrict__ out,
    __half* __restrict__ out16, __half* __restrict__ outhi, __half* __restrict__ outlo,
    int N, int mode)
{
    extern __shared__ uint32_t smem_u[];
    uint32_t* Ahi = smem_u;                   // [128][STR] half2 words
    uint32_t* Alo = Ahi + 128 * STR;
    uint32_t* Whi = Alo + 128 * STR;
    uint32_t* Wlo = Whi + 128 * STR;
    float* bias_s = (float*)(Wlo + 128 * STR);  // [128]
    float* red    = bias_s + 128;               // [128][4]
    float* scl    = red + 512;                  // [128]

    int tid  = threadIdx.x;
    int lane = tid & 31;
    int warp = tid >> 5;
    int rbase = (warp >> 2) * 32;   // 4 row groups
    int cbase = (warp & 3) * 32;    // 4 col groups
    size_t m0 = (size_t)blockIdx.x * 128;

    if (tid < 128) bias_s[tid] = bias[tid];

    // ---- prologue: pure vector copy into padded smem tiles ----
#pragma unroll
    for (int i = 0; i < 4; i++) {
        int idx = tid + i * 512;       // 2048 uint4 slots per matrix
        int row = idx >> 4;            // 0..127
        int q   = idx & 15;            // 16 uint4 per row
        int dst = row * STR + q * 4;
        size_t ga = (m0 + row) * D + q * 8;
        size_t gw = (size_t)row * D + q * 8;
        *reinterpret_cast<uint4*>(&Ahi[dst]) = *reinterpret_cast<const uint4*>(&Ahi_g[ga]);
        *reinterpret_cast<uint4*>(&Alo[dst]) = *reinterpret_cast<const uint4*>(&Alo_g[ga]);
        *reinterpret_cast<uint4*>(&Whi[dst]) = *reinterpret_cast<const uint4*>(&Whi_g[gw]);
        *reinterpret_cast<uint4*>(&Wlo[dst]) = *reinterpret_cast<const uint4*>(&Wlo_g[gw]);
    }
    __syncthreads();

    float acc[2][4][4];
#pragma unroll
    for (int rt = 0; rt < 2; rt++)
#pragma unroll
        for (int ct = 0; ct < 4; ct++)
#pragma unroll
            for (int q = 0; q < 4; q++) acc[rt][ct][q] = 0.0f;

    int c = lane & 3;
    int g = lane >> 2;

#pragma unroll
    for (int ks = 0; ks < 8; ks++) {
        int k0 = ks * 8;                    // word offset of this k16 step
        uint32_t ah[2][4], al[2][4];
#pragma unroll
        for (int rt = 0; rt < 2; rt++) {
            int r0 = rbase + rt * 16 + g;
            int b0 = r0 * STR + k0 + c;
            int b1 = (r0 + 8) * STR + k0 + c;
            ah[rt][0] = Ahi[b0];     ah[rt][1] = Ahi[b1];
            ah[rt][2] = Ahi[b0 + 4]; ah[rt][3] = Ahi[b1 + 4];
            al[rt][0] = Alo[b0];     al[rt][1] = Alo[b1];
            al[rt][2] = Alo[b0 + 4]; al[rt][3] = Alo[b1 + 4];
        }
#pragma unroll
        for (int ct = 0; ct < 4; ct++) {
            int col = cbase + ct * 8 + g;
            int wb = col * STR + k0 + c;
            uint32_t bh0 = Whi[wb], bh1 = Whi[wb + 4];
            uint32_t bl0 = Wlo[wb], bl1 = Wlo[wb + 4];
#pragma unroll
            for (int rt = 0; rt < 2; rt++) {
                mma_f16(acc[rt][ct], ah[rt][0], ah[rt][1], ah[rt][2], ah[rt][3], bh0, bh1);
                mma_f16(acc[rt][ct], ah[rt][0], ah[rt][1], ah[rt][2], ah[rt][3], bl0, bl1);
                mma_f16(acc[rt][ct], al[rt][0], al[rt][1], al[rt][2], al[rt][3], bh0, bh1);
            }
        }
    }

    // ---- epilogue: bias add + per-row sumsq ----
    float prow[2][2];
#pragma unroll
    for (int rt = 0; rt < 2; rt++) {
        prow[rt][0] = 0.f; prow[rt][1] = 0.f;
#pragma unroll
        for (int ct = 0; ct < 4; ct++) {
            int colb = cbase + ct * 8 + 2 * c;
            float u0 = acc[rt][ct][0] + bias_s[colb];
            float u1 = acc[rt][ct][1] + bias_s[colb + 1];
            float u2 = acc[rt][ct][2] + bias_s[colb];
            float u3 = acc[rt][ct][3] + bias_s[colb + 1];
            acc[rt][ct][0] = u0; acc[rt][ct][1] = u1;
            acc[rt][ct][2] = u2; acc[rt][ct][3] = u3;
            prow[rt][0] += u0 * u0 + u1 * u1;
            prow[rt][1] += u2 * u2 + u3 * u3;
        }
#pragma unroll
        for (int o = 1; o < 4; o <<= 1) {
            prow[rt][0] += __shfl_xor_sync(0xffffffffu, prow[rt][0], o);
            prow[rt][1] += __shfl_xor_sync(0xffffffffu, prow[rt][1], o);
        }
    }
    int cg = warp & 3;
    if (c == 0) {
#pragma unroll
        for (int rt = 0; rt < 2; rt++) {
            int r0 = rbase + rt * 16 + g;
            red[r0 * 4 + cg]       = prow[rt][0];
            red[(r0 + 8) * 4 + cg] = prow[rt][1];
        }
    }
    __syncthreads();
    if (tid < 128) {
        float s = red[tid * 4] + red[tid * 4 + 1] + red[tid * 4 + 2] + red[tid * 4 + 3];
        float n = sqrtf(s);
        scl[tid] = (mode == 1) ? chain_ep(n) : chain_epl(n);
    }
    __syncthreads();

    // ---- scaled store ----
#pragma unroll
    for (int rt = 0; rt < 2; rt++) {
        int r0 = rbase + rt * 16 + g;
        float s0 = scl[r0];
        float s1 = scl[r0 + 8];
        size_t gm0 = m0 + r0;
        size_t gm1 = gm0 + 8;
#pragma unroll
        for (int ct = 0; ct < 4; ct++) {
            int colb = cbase + ct * 8 + 2 * c;
            if (mode == 0) {
                if (gm0 < (size_t)N) {
                    __half2 hv = __floats2half2_rn(acc[rt][ct][0] * s0, acc[rt][ct][1] * s0);
                    *reinterpret_cast<__half2*>(&out16[gm0 * D + colb]) = hv;
                }
                if (gm1 < (size_t)N) {
                    __half2 hv = __floats2half2_rn(acc[rt][ct][2] * s1, acc[rt][ct][3] * s1);
                    *reinterpret_cast<__half2*>(&out16[gm1 * D + colb]) = hv;
                }
            } else if (mode == 1) {
                if (gm0 < (size_t)N) {
                    float2 o = make_float2(acc[rt][ct][0] * s0, acc[rt][ct][1] * s0);
                    *reinterpret_cast<float2*>(&out[gm0 * D + colb]) = o;
                }
                if (gm1 < (size_t)N) {
                    float2 o = make_float2(acc[rt][ct][2] * s1, acc[rt][ct][3] * s1);
                    *reinterpret_cast<float2*>(&out[gm1 * D + colb]) = o;
                }
            } else {
                if (gm0 < (size_t)N) {
                    uint32_t h, l;
                    split2(acc[rt][ct][0] * s0, acc[rt][ct][1] * s0, h, l);
                    *reinterpret_cast<uint32_t*>(&outhi[gm0 * D + colb]) = h;
                    *reinterpret_cast<uint32_t*>(&outlo[gm0 * D + colb]) = l;
                }
                if (gm1 < (size_t)N) {
                    uint32_t h, l;
                    split2(acc[rt][ct][2] * s1, acc[rt][ct][3] * s1, h, l);
                    *reinterpret_cast<uint32_t*>(&outhi[gm1 * D + colb]) = h;
                    *reinterpret_cast<uint32_t*>(&outlo[gm1 * D + colb]) = l;
                }
            }
        }
    }
}

// ---------------- host ------------------------------------------------------
extern "C" void kernel_launch(void* const* d_in, const int* in_sizes, int n_in,
                              void* d_out, int out_size)
{
    const float* x     = (const float*)d_in[0];
    const int*   ei    = (const int*)d_in[1];
    const float* msg_W = (const float*)d_in[2];
    const float* msg_b = (const float*)d_in[3];
    const float* upd_W = (const float*)d_in[4];
    const float* upd_b = (const float*)d_in[5];
    float* outp = (float*)d_out;

    int N = in_sizes[0] / D;
    int E = in_sizes[1] / 2;
    int L = in_sizes[3] / D;
    if (N > MAXN || E > MAXE || L > MAXL) return;

    const int* src = ei;
    const int* dst = ei + E;

    __half *p_t16, *p_a0hi, *p_a0lo, *p_a1hi, *p_a1lo, *p_whi, *p_wlo;
    int *p_deg;
    cudaGetSymbolAddress((void**)&p_t16,  g_t16);
    cudaGetSymbolAddress((void**)&p_a0hi, g_a0hi);
    cudaGetSymbolAddress((void**)&p_a0lo, g_a0lo);
    cudaGetSymbolAddress((void**)&p_a1hi, g_a1hi);
    cudaGetSymbolAddress((void**)&p_a1lo, g_a1lo);
    cudaGetSymbolAddress((void**)&p_whi,  g_whi);
    cudaGetSymbolAddress((void**)&p_wlo,  g_wlo);
    cudaGetSymbolAddress((void**)&p_deg,  g_deg);

    const int SMEM = (4 * 128 * STR + 128 + 512 + 128) * (int)sizeof(uint32_t);
    static bool init_done = false;
    static cudaStream_t s1;
    static cudaEvent_t ev_fork, ev_w, ev_join;
    if (!init_done) {
        cudaFuncSetAttribute(gemm_hyp_tc_kernel,
                             cudaFuncAttributeMaxDynamicSharedMemorySize, SMEM);
        cudaStreamCreateWithFlags(&s1, cudaStreamNonBlocking);
        cudaEventCreateWithFlags(&ev_fork, cudaEventDisableTiming);
        cudaEventCreateWithFlags(&ev_w, cudaEventDisableTiming);
        cudaEventCreateWithFlags(&ev_join, cudaEventDisableTiming);
        init_done = true;
    }

    cudaStream_t s0 = 0;
    int wl = L * D * D;         // halves per weight block

    // ---- fork: weight pre-split then CSR build on side stream ----
    cudaEventRecord(ev_fork, s0);
    cudaStreamWaitEvent(s1, ev_fork, 0);
    {
        int n2 = wl / 2;
        wsplit_kernel<<<(n2 + 255) / 256, 256, 0, s1>>>(msg_W, p_whi, p_wlo, n2);
        wsplit_kernel<<<(n2 + 255) / 256, 256, 0, s1>>>(upd_W, p_whi + wl, p_wlo + wl, n2);
    }
    cudaEventRecord(ev_w, s1);
    zero_int_kernel<<<(N + 255) / 256, 256, 0, s1>>>(p_deg, N);
    hist_kernel<<<(E + 255) / 256, 256, 0, s1>>>(dst, E);
    scan_kernel<<<1, 1024, 0, s1>>>(N);
    fill_kernel<<<(E + 255) / 256, 256, 0, s1>>>(src, dst, E);
    cudaEventRecord(ev_join, s1);

    int gemm_blocks  = (N + 127) / 128;
    int warp_blocksN = (N * 32 + 255) / 256;

    prep_log0_kernel<<<warp_blocksN, 256>>>(x, p_a0hi, p_a0lo, N);
    cudaStreamWaitEvent(s0, ev_w, 0);

    bool joined = false;
    for (int l = 0; l < L; l++) {
        // message hyp_linear -> fp16 tangent messages t
        gemm_hyp_tc_kernel<<<gemm_blocks, 512, SMEM>>>(
            p_a0hi, p_a0lo, p_whi + (size_t)l * D * D, p_wlo + (size_t)l * D * D,
            msg_b + (size_t)l * D, nullptr, p_t16, nullptr, nullptr, N, 0);
        if (!joined) { cudaStreamWaitEvent(s0, ev_join, 0); joined = true; }
        // gather + mean + chain -> pre-split tangent into A1
        agg_kernel<<<warp_blocksN, 256>>>(p_a1hi, p_a1lo, N);
        // update hyp_linear
        if (l == L - 1) {
            gemm_hyp_tc_kernel<<<gemm_blocks, 512, SMEM>>>(
                p_a1hi, p_a1lo, p_whi + wl + (size_t)l * D * D, p_wlo + wl + (size_t)l * D * D,
                upd_b + (size_t)l * D, outp, nullptr, nullptr, nullptr, N, 1);
        } else {
            gemm_hyp_tc_kernel<<<gemm_blocks, 512, SMEM>>>(
                p_a1hi, p_a1lo, p_whi + wl + (size_t)l * D * D, p_wlo + wl + (size_t)l * D * D,
                upd_b + (size_t)l * D, nullptr, nullptr, p_a0hi, p_a0lo, N, 2);
        }
    }
}

// round 12
// speedup vs baseline: 1.2031x; 1.2031x over previous
#include <cuda_runtime.h>
#include <cuda_fp16.h>
#include <math.h>
#include <stdint.h>

#define EPS 1e-5f
#define MAX_NORM 0.95f
#define D 128
#define MAXN 50000
#define MAXE 800000

// ---------------- scratch (static device globals) ---------------------------
__device__ float  g_v[MAXN * D];     // tangent vectors (GEMM input)
__device__ __half g_t16[MAXN * D];   // fp16 message tangents (gather source)
__device__ float  g_h[MAXN * D];     // inter-layer tangent state (fp32)
__device__ int    g_deg[MAXN];
__device__ int    g_off[MAXN + 1];
__device__ int    g_cur[MAXN];
__device__ int    g_csrc[MAXE];

// ---------------- scalar chains ---------------------------------------------
__device__ __forceinline__ float s_log0(float n) {
    float nm  = fmaxf(n, EPS);
    float arg = fminf(nm, 1.0f - EPS);
    return atanhf(arg) / nm;
}
__device__ __forceinline__ float chain_epl(float n) {
    float nm = fmaxf(n, EPS);
    float a  = tanhf(nm) / nm;
    float na = n * a;
    float b  = (na > MAX_NORM) ? MAX_NORM / fmaxf(na, EPS) : 1.0f;
    float nb = na * b;
    float nbm = fmaxf(nb, EPS);
    float arg = fminf(nbm, 1.0f - EPS);
    float c  = atanhf(arg) / nbm;
    return a * b * c;
}
__device__ __forceinline__ float chain_ep(float n) {
    float nm = fmaxf(n, EPS);
    float a  = tanhf(nm) / nm;
    float na = n * a;
    float b  = (na > MAX_NORM) ? MAX_NORM / fmaxf(na, EPS) : 1.0f;
    return a * b;
}

// ---------------- fp16 mma helper -------------------------------------------
__device__ __forceinline__ void mma_f16(float* d, uint32_t a0, uint32_t a1,
                                        uint32_t a2, uint32_t a3,
                                        uint32_t b0, uint32_t b1) {
    asm volatile(
        "mma.sync.aligned.m16n8k16.row.col.f32.f16.f16.f32 "
        "{%0,%1,%2,%3}, {%4,%5,%6,%7}, {%8,%9}, {%0,%1,%2,%3};\n"
        : "+f"(d[0]), "+f"(d[1]), "+f"(d[2]), "+f"(d[3])
        : "r"(a0), "r"(a1), "r"(a2), "r"(a3), "r"(b0), "r"(b1));
}
// split float pair into fp16 hi + fp16 residual lo (packed half2 words)
__device__ __forceinline__ void split2(float x, float y, uint32_t& hi, uint32_t& lo) {
    __half2 h = __floats2half2_rn(x, y);
    float2 hf = __half22float2(h);
    __half2 l = __floats2half2_rn(x - hf.x, y - hf.y);
    hi = *reinterpret_cast<uint32_t*>(&h);
    lo = *reinterpret_cast<uint32_t*>(&l);
}

// ---------------- CSR construction ------------------------------------------
__global__ void zero_int_kernel(int* __restrict__ p, int n) {
    int i = blockIdx.x * blockDim.x + threadIdx.x;
    if (i < n) p[i] = 0;
}
__global__ void hist_kernel(const int* __restrict__ dst, int E) {
    int e = blockIdx.x * blockDim.x + threadIdx.x;
    if (e < E) atomicAdd(&g_deg[dst[e]], 1);
}
__global__ void scan_kernel(int N) {
    int lane = threadIdx.x & 31, wid = threadIdx.x >> 5;
    __shared__ int wsum[32];
    __shared__ int running;
    if (threadIdx.x == 0) running = 0;
    __syncthreads();
    for (int base = 0; base < N; base += 1024) {
        int i = base + (int)threadIdx.x;
        int v = (i < N) ? g_deg[i] : 0;
        int x = v;
#pragma unroll
        for (int o = 1; o < 32; o <<= 1) {
            int y = __shfl_up_sync(0xffffffffu, x, o);
            if (lane >= o) x += y;
        }
        if (lane == 31) wsum[wid] = x;
        __syncthreads();
        if (wid == 0) {
            int s = wsum[lane];
#pragma unroll
            for (int o = 1; o < 32; o <<= 1) {
                int y = __shfl_up_sync(0xffffffffu, s, o);
                if (lane >= o) s += y;
            }
            wsum[lane] = s;
        }
        __syncthreads();
        int warp_prefix = (wid == 0) ? 0 : wsum[wid - 1];
        int excl = running + warp_prefix + (x - v);
        if (i < N) { g_off[i] = excl; g_cur[i] = excl; }
        int tile_total = wsum[31];
        __syncthreads();
        if (threadIdx.x == 0) running += tile_total;
        __syncthreads();
    }
    if (threadIdx.x == 0) g_off[N] = running;
}
__global__ void fill_kernel(const int* __restrict__ src, const int* __restrict__ dst, int E) {
    int e = blockIdx.x * blockDim.x + threadIdx.x;
    if (e < E) {
        int p = atomicAdd(&g_cur[dst[e]], 1);
        g_csrc[p] = src[e];
    }
}

// ---------------- prep: v = log0(x) -----------------------------------------
__global__ void prep_log0_kernel(const float* __restrict__ in, float* __restrict__ out, int N) {
    int w    = (blockIdx.x * blockDim.x + threadIdx.x) >> 5;
    int lane = threadIdx.x & 31;
    if (w >= N) return;
    float4 v = *reinterpret_cast<const float4*>(&in[(size_t)w * D + lane * 4]);
    float p = v.x * v.x + v.y * v.y + v.z * v.z + v.w * v.w;
#pragma unroll
    for (int off = 16; off; off >>= 1) p += __shfl_xor_sync(0xffffffffu, p, off);
    float s = s_log0(sqrtf(p));
    v.x *= s; v.y *= s; v.z *= s; v.w *= s;
    *reinterpret_cast<float4*>(&out[(size_t)w * D + lane * 4]) = v;
}

// ---------------- fused gather(fp16) + mean + chain_epl ---------------------
__global__ void agg_kernel(float* __restrict__ out, int N) {
    int w    = (blockIdx.x * blockDim.x + threadIdx.x) >> 5;
    int lane = threadIdx.x & 31;
    if (w >= N) return;
    int beg = g_off[w], end = g_off[w + 1];
    float ax = 0.f, ay = 0.f, az = 0.f, aw = 0.f;
    int e = beg;
    int col = lane * 4;
#pragma unroll 1
    for (; e + 4 <= end; e += 4) {
        int s0 = g_csrc[e], s1 = g_csrc[e + 1], s2 = g_csrc[e + 2], s3 = g_csrc[e + 3];
        uint2 u0 = *reinterpret_cast<const uint2*>(&g_t16[(size_t)s0 * D + col]);
        uint2 u1 = *reinterpret_cast<const uint2*>(&g_t16[(size_t)s1 * D + col]);
        uint2 u2 = *reinterpret_cast<const uint2*>(&g_t16[(size_t)s2 * D + col]);
        uint2 u3 = *reinterpret_cast<const uint2*>(&g_t16[(size_t)s3 * D + col]);
        float2 a, b;
        a = __half22float2(*(__half2*)&u0.x); b = __half22float2(*(__half2*)&u0.y);
        ax += a.x; ay += a.y; az += b.x; aw += b.y;
        a = __half22float2(*(__half2*)&u1.x); b = __half22float2(*(__half2*)&u1.y);
        ax += a.x; ay += a.y; az += b.x; aw += b.y;
        a = __half22float2(*(__half2*)&u2.x); b = __half22float2(*(__half2*)&u2.y);
        ax += a.x; ay += a.y; az += b.x; aw += b.y;
        a = __half22float2(*(__half2*)&u3.x); b = __half22float2(*(__half2*)&u3.y);
        ax += a.x; ay += a.y; az += b.x; aw += b.y;
    }
    for (; e < end; e++) {
        int s0 = g_csrc[e];
        uint2 u0 = *reinterpret_cast<const uint2*>(&g_t16[(size_t)s0 * D + col]);
        float2 a = __half22float2(*(__half2*)&u0.x);
        float2 b = __half22float2(*(__half2*)&u0.y);
        ax += a.x; ay += a.y; az += b.x; aw += b.y;
    }
    float inv = 1.0f / fmaxf((float)(end - beg), 1.0f);
    ax *= inv; ay *= inv; az *= inv; aw *= inv;
    float p = ax * ax + ay * ay + az * az + aw * aw;
#pragma unroll
    for (int off = 16; off; off >>= 1) p += __shfl_xor_sync(0xffffffffu, p, off);
    float s = chain_epl(sqrtf(p));
    float4 o = make_float4(ax * s, ay * s, az * s, aw * s);
    *reinterpret_cast<float4*>(&out[(size_t)w * D + col]) = o;
}

// ---------------- 2-term fp16-split tensor-core GEMM + hyperbolic epilogue --
// CTA: 128x128 output tile, K=128 resident. 16 warps, warp tile 32x32.
// A split hi+lo (exact to 2^-22); W only hi. D = (Ahi+Alo)@Whi ~= A@Whi.
// Dropped A@Wlo term: ~2.8e-4 RMS relative per GEMM (within error budget).
// mode 0: chain_epl, fp16 store (message tangents)
// mode 1: chain_ep,  fp32 store (final output)
// mode 2: chain_epl, fp32 store (inter-layer tangent)
#define STR 68   // half2-word row stride: 68 mod 32 == 4 -> banks 4g+c, conflict-free

__global__ __launch_bounds__(512) void gemm_hyp_tc_kernel(
    const float* __restrict__ V, const float* __restrict__ W,
    const float* __restrict__ bias, float* __restrict__ out,
    __half* __restrict__ out16, int N, int mode)
{
    extern __shared__ uint32_t smem_u[];
    uint32_t* Ahi = smem_u;                 // [128][STR] half2 words
    uint32_t* Alo = Ahi + 128 * STR;
    uint32_t* Whi = Alo + 128 * STR;
    float* bias_s = (float*)(Whi + 128 * STR);  // [128]
    float* red    = bias_s + 128;               // [128][4]
    float* scl    = red + 512;                  // [128]

    int tid  = threadIdx.x;
    int lane = tid & 31;
    int warp = tid >> 5;
    int rbase = (warp >> 2) * 32;   // 4 row groups
    int cbase = (warp & 3) * 32;    // 4 col groups
    int m0 = blockIdx.x * 128;

    if (tid < 128) bias_s[tid] = bias[tid];

    // ---- load tiles; A split hi/lo, W hi only ----
#pragma unroll
    for (int i = 0; i < 8; i++) {
        int idx = tid + i * 512;            // 4096 float4 slots
        int row = idx >> 5;
        int c4  = (idx & 31) * 4;           // float col, multiple of 4
        int wofs = row * STR + (c4 >> 1);   // half2-word offset

        float4 av = make_float4(0.f, 0.f, 0.f, 0.f);
        int gm = m0 + row;
        if (gm < N) av = *reinterpret_cast<const float4*>(&V[(size_t)gm * D + c4]);
        uint32_t h0, l0, h1, l1;
        split2(av.x, av.y, h0, l0);
        split2(av.z, av.w, h1, l1);
        Ahi[wofs] = h0; Ahi[wofs + 1] = h1;
        Alo[wofs] = l0; Alo[wofs + 1] = l1;

        float4 wv = *reinterpret_cast<const float4*>(&W[(size_t)row * D + c4]);
        __half2 wh0 = __floats2half2_rn(wv.x, wv.y);
        __half2 wh1 = __floats2half2_rn(wv.z, wv.w);
        Whi[wofs]     = *reinterpret_cast<uint32_t*>(&wh0);
        Whi[wofs + 1] = *reinterpret_cast<uint32_t*>(&wh1);
    }
    __syncthreads();

    float acc[2][4][4];
#pragma unroll
    for (int rt = 0; rt < 2; rt++)
#pragma unroll
        for (int ct = 0; ct < 4; ct++)
#pragma unroll
            for (int q = 0; q < 4; q++) acc[rt][ct][q] = 0.0f;

    int c = lane & 3;
    int g = lane >> 2;

#pragma unroll
    for (int ks = 0; ks < 8; ks++) {
        int k0 = ks * 8;                    // word offset of this k16 step
        uint32_t ah[2][4], al[2][4];
#pragma unroll
        for (int rt = 0; rt < 2; rt++) {
            int r0 = rbase + rt * 16 + g;
            int b0 = r0 * STR + k0 + c;
            int b1 = (r0 + 8) * STR + k0 + c;
            ah[rt][0] = Ahi[b0];     ah[rt][1] = Ahi[b1];
            ah[rt][2] = Ahi[b0 + 4]; ah[rt][3] = Ahi[b1 + 4];
            al[rt][0] = Alo[b0];     al[rt][1] = Alo[b1];
            al[rt][2] = Alo[b0 + 4]; al[rt][3] = Alo[b1 + 4];
        }
#pragma unroll
        for (int ct = 0; ct < 4; ct++) {
            int col = cbase + ct * 8 + g;
            int wb = col * STR + k0 + c;
            uint32_t bh0 = Whi[wb], bh1 = Whi[wb + 4];
#pragma unroll
            for (int rt = 0; rt < 2; rt++) {
                mma_f16(acc[rt][ct], ah[rt][0], ah[rt][1], ah[rt][2], ah[rt][3], bh0, bh1);
                mma_f16(acc[rt][ct], al[rt][0], al[rt][1], al[rt][2], al[rt][3], bh0, bh1);
            }
        }
    }

    // ---- epilogue: bias add + per-row sumsq ----
    float prow[2][2];
#pragma unroll
    for (int rt = 0; rt < 2; rt++) {
        prow[rt][0] = 0.f; prow[rt][1] = 0.f;
#pragma unroll
        for (int ct = 0; ct < 4; ct++) {
            int colb = cbase + ct * 8 + 2 * c;
            float u0 = acc[rt][ct][0] + bias_s[colb];
            float u1 = acc[rt][ct][1] + bias_s[colb + 1];
            float u2 = acc[rt][ct][2] + bias_s[colb];
            float u3 = acc[rt][ct][3] + bias_s[colb + 1];
            acc[rt][ct][0] = u0; acc[rt][ct][1] = u1;
            acc[rt][ct][2] = u2; acc[rt][ct][3] = u3;
            prow[rt][0] += u0 * u0 + u1 * u1;
            prow[rt][1] += u2 * u2 + u3 * u3;
        }
#pragma unroll
        for (int o = 1; o < 4; o <<= 1) {
            prow[rt][0] += __shfl_xor_sync(0xffffffffu, prow[rt][0], o);
            prow[rt][1] += __shfl_xor_sync(0xffffffffu, prow[rt][1], o);
        }
    }
    int cg = warp & 3;
    if (c == 0) {
#pragma unroll
        for (int rt = 0; rt < 2; rt++) {
            int r0 = rbase + rt * 16 + g;
            red[r0 * 4 + cg]       = prow[rt][0];
            red[(r0 + 8) * 4 + cg] = prow[rt][1];
        }
    }
    __syncthreads();
    if (tid < 128) {
        float s = red[tid * 4] + red[tid * 4 + 1] + red[tid * 4 + 2] + red[tid * 4 + 3];
        float n = sqrtf(s);
        scl[tid] = (mode == 1) ? chain_ep(n) : chain_epl(n);
    }
    __syncthreads();

    // ---- scaled store ----
#pragma unroll
    for (int rt = 0; rt < 2; rt++) {
        int r0 = rbase + rt * 16 + g;
        float s0 = scl[r0];
        float s1 = scl[r0 + 8];
        int gm0 = m0 + r0;
        int gm1 = gm0 + 8;
#pragma unroll
        for (int ct = 0; ct < 4; ct++) {
            int colb = cbase + ct * 8 + 2 * c;
            if (mode == 0) {
                if (gm0 < N) {
                    __half2 hv = __floats2half2_rn(acc[rt][ct][0] * s0, acc[rt][ct][1] * s0);
                    *reinterpret_cast<__half2*>(&out16[(size_t)gm0 * D + colb]) = hv;
                }
                if (gm1 < N) {
                    __half2 hv = __floats2half2_rn(acc[rt][ct][2] * s1, acc[rt][ct][3] * s1);
                    *reinterpret_cast<__half2*>(&out16[(size_t)gm1 * D + colb]) = hv;
                }
            } else {
                if (gm0 < N) {
                    float2 o = make_float2(acc[rt][ct][0] * s0, acc[rt][ct][1] * s0);
                    *reinterpret_cast<float2*>(&out[(size_t)gm0 * D + colb]) = o;
                }
                if (gm1 < N) {
                    float2 o = make_float2(acc[rt][ct][2] * s1, acc[rt][ct][3] * s1);
                    *reinterpret_cast<float2*>(&out[(size_t)gm1 * D + colb]) = o;
                }
            }
        }
    }
}

// ---------------- host ------------------------------------------------------
extern "C" void kernel_launch(void* const* d_in, const int* in_sizes, int n_in,
                              void* d_out, int out_size)
{
    const float* x     = (const float*)d_in[0];
    const int*   ei    = (const int*)d_in[1];
    const float* msg_W = (const float*)d_in[2];
    const float* msg_b = (const float*)d_in[3];
    const float* upd_W = (const float*)d_in[4];
    const float* upd_b = (const float*)d_in[5];
    float* outp = (float*)d_out;

    int N = in_sizes[0] / D;
    int E = in_sizes[1] / 2;
    int L = in_sizes[3] / D;
    if (N > MAXN || E > MAXE) return;

    const int* src = ei;
    const int* dst = ei + E;

    float *p_v, *p_h;
    __half* p_t16;
    int *p_deg;
    cudaGetSymbolAddress((void**)&p_v,   g_v);
    cudaGetSymbolAddress((void**)&p_t16, g_t16);
    cudaGetSymbolAddress((void**)&p_h,   g_h);
    cudaGetSymbolAddress((void**)&p_deg, g_deg);

    const int SMEM = (3 * 128 * STR + 128 + 512 + 128) * (int)sizeof(uint32_t);
    static bool init_done = false;
    static cudaStream_t s1;
    static cudaEvent_t ev_fork, ev_join;
    if (!init_done) {
        cudaFuncSetAttribute(gemm_hyp_tc_kernel,
                             cudaFuncAttributeMaxDynamicSharedMemorySize, SMEM);
        cudaStreamCreateWithFlags(&s1, cudaStreamNonBlocking);
        cudaEventCreateWithFlags(&ev_fork, cudaEventDisableTiming);
        cudaEventCreateWithFlags(&ev_join, cudaEventDisableTiming);
        init_done = true;
    }

    cudaStream_t s0 = 0;

    // ---- fork: CSR build on side stream ----
    cudaEventRecord(ev_fork, s0);
    cudaStreamWaitEvent(s1, ev_fork, 0);
    zero_int_kernel<<<(N + 255) / 256, 256, 0, s1>>>(p_deg, N);
    hist_kernel<<<(E + 255) / 256, 256, 0, s1>>>(dst, E);
    scan_kernel<<<1, 1024, 0, s1>>>(N);
    fill_kernel<<<(E + 255) / 256, 256, 0, s1>>>(src, dst, E);
    cudaEventRecord(ev_join, s1);

    int gemm_blocks  = (N + 127) / 128;
    int warp_blocksN = (N * 32 + 255) / 256;

    prep_log0_kernel<<<warp_blocksN, 256>>>(x, p_v, N);

    bool joined = false;
    const float* v_in = p_v;
    for (int l = 0; l < L; l++) {
        gemm_hyp_tc_kernel<<<gemm_blocks, 512, SMEM>>>(v_in, msg_W + (size_t)l * D * D,
                                                       msg_b + (size_t)l * D,
                                                       nullptr, p_t16, N, 0);
        if (!joined) { cudaStreamWaitEvent(s0, ev_join, 0); joined = true; }
        agg_kernel<<<warp_blocksN, 256>>>(p_v, N);
        if (l == L - 1) {
            gemm_hyp_tc_kernel<<<gemm_blocks, 512, SMEM>>>(p_v, upd_W + (size_t)l * D * D,
                                                           upd_b + (size_t)l * D,
                                                           outp, nullptr, N, 1);
        } else {
            gemm_hyp_tc_kernel<<<gemm_blocks, 512, SMEM>>>(p_v, upd_W + (size_t)l * D * D,
                                                           upd_b + (size_t)l * D,
                                                           p_h, nullptr, N, 2);
            v_in = p_h;
        }
    }
}

// round 15
// speedup vs baseline: 1.2428x; 1.0330x over previous
#include <cuda_runtime.h>
#include <cuda_fp16.h>
#include <math.h>
#include <stdint.h>

#define EPS 1e-5f
#define MAX_NORM 0.95f
#define D 128
#define MAXN 50000
#define MAXE 800000

// ---------------- scratch (static device globals) ---------------------------
__device__ float  g_v[MAXN * D];     // tangent vectors (GEMM input)
__device__ __half g_t16[MAXN * D];   // fp16 message tangents (gather source)
__device__ float  g_h[MAXN * D];     // inter-layer tangent state (fp32)
__device__ int    g_deg[MAXN];
__device__ int    g_off[MAXN + 1];
__device__ int    g_cur[MAXN];
__device__ int    g_csrc[MAXE];

// ---------------- scalar chains ---------------------------------------------
__device__ __forceinline__ float s_log0(float n) {
    float nm  = fmaxf(n, EPS);
    float arg = fminf(nm, 1.0f - EPS);
    return atanhf(arg) / nm;
}
__device__ __forceinline__ float chain_epl(float n) {
    float nm = fmaxf(n, EPS);
    float a  = tanhf(nm) / nm;
    float na = n * a;
    float b  = (na > MAX_NORM) ? MAX_NORM / fmaxf(na, EPS) : 1.0f;
    float nb = na * b;
    float nbm = fmaxf(nb, EPS);
    float arg = fminf(nbm, 1.0f - EPS);
    float c  = atanhf(arg) / nbm;
    return a * b * c;
}
__device__ __forceinline__ float chain_ep(float n) {
    float nm = fmaxf(n, EPS);
    float a  = tanhf(nm) / nm;
    float na = n * a;
    float b  = (na > MAX_NORM) ? MAX_NORM / fmaxf(na, EPS) : 1.0f;
    return a * b;
}

// ---------------- fp16 mma helper -------------------------------------------
__device__ __forceinline__ void mma_f16(float* d, uint32_t a0, uint32_t a1,
                                        uint32_t a2, uint32_t a3,
                                        uint32_t b0, uint32_t b1) {
    asm volatile(
        "mma.sync.aligned.m16n8k16.row.col.f32.f16.f16.f32 "
        "{%0,%1,%2,%3}, {%4,%5,%6,%7}, {%8,%9}, {%0,%1,%2,%3};\n"
        : "+f"(d[0]), "+f"(d[1]), "+f"(d[2]), "+f"(d[3])
        : "r"(a0), "r"(a1), "r"(a2), "r"(a3), "r"(b0), "r"(b1));
}
// split float pair into fp16 hi + fp16 residual lo (packed half2 words)
__device__ __forceinline__ void split2(float x, float y, uint32_t& hi, uint32_t& lo) {
    __half2 h = __floats2half2_rn(x, y);
    float2 hf = __half22float2(h);
    __half2 l = __floats2half2_rn(x - hf.x, y - hf.y);
    hi = *reinterpret_cast<uint32_t*>(&h);
    lo = *reinterpret_cast<uint32_t*>(&l);
}

// ---------------- CSR construction ------------------------------------------
__global__ void zero_int_kernel(int* __restrict__ p, int n) {
    int i = blockIdx.x * blockDim.x + threadIdx.x;
    if (i < n) p[i] = 0;
}
__global__ void hist_kernel(const int* __restrict__ dst, int E) {
    int e = blockIdx.x * blockDim.x + threadIdx.x;
    if (e < E) atomicAdd(&g_deg[dst[e]], 1);
}
__global__ void scan_kernel(int N) {
    int lane = threadIdx.x & 31, wid = threadIdx.x >> 5;
    __shared__ int wsum[32];
    __shared__ int running;
    if (threadIdx.x == 0) running = 0;
    __syncthreads();
    for (int base = 0; base < N; base += 1024) {
        int i = base + (int)threadIdx.x;
        int v = (i < N) ? g_deg[i] : 0;
        int x = v;
#pragma unroll
        for (int o = 1; o < 32; o <<= 1) {
            int y = __shfl_up_sync(0xffffffffu, x, o);
            if (lane >= o) x += y;
        }
        if (lane == 31) wsum[wid] = x;
        __syncthreads();
        if (wid == 0) {
            int s = wsum[lane];
#pragma unroll
            for (int o = 1; o < 32; o <<= 1) {
                int y = __shfl_up_sync(0xffffffffu, s, o);
                if (lane >= o) s += y;
            }
            wsum[lane] = s;
        }
        __syncthreads();
        int warp_prefix = (wid == 0) ? 0 : wsum[wid - 1];
        int excl = running + warp_prefix + (x - v);
        if (i < N) { g_off[i] = excl; g_cur[i] = excl; }
        int tile_total = wsum[31];
        __syncthreads();
        if (threadIdx.x == 0) running += tile_total;
        __syncthreads();
    }
    if (threadIdx.x == 0) g_off[N] = running;
}
__global__ void fill_kernel(const int* __restrict__ src, const int* __restrict__ dst, int E) {
    int e = blockIdx.x * blockDim.x + threadIdx.x;
    if (e < E) {
        int p = atomicAdd(&g_cur[dst[e]], 1);
        g_csrc[p] = src[e];
    }
}

// ---------------- prep: v = log0(x) -----------------------------------------
__global__ void prep_log0_kernel(const float* __restrict__ in, float* __restrict__ out, int N) {
    int w    = (blockIdx.x * blockDim.x + threadIdx.x) >> 5;
    int lane = threadIdx.x & 31;
    if (w >= N) return;
    float4 v = *reinterpret_cast<const float4*>(&in[(size_t)w * D + lane * 4]);
    float p = v.x * v.x + v.y * v.y + v.z * v.z + v.w * v.w;
#pragma unroll
    for (int off = 16; off; off >>= 1) p += __shfl_xor_sync(0xffffffffu, p, off);
    float s = s_log0(sqrtf(p));
    v.x *= s; v.y *= s; v.z *= s; v.w *= s;
    *reinterpret_cast<float4*>(&out[(size_t)w * D + lane * 4]) = v;
}

// ---------------- fused gather(fp16) + mean + chain_epl ---------------------
__global__ void agg_kernel(float* __restrict__ out, int N) {
    int w    = (blockIdx.x * blockDim.x + threadIdx.x) >> 5;
    int lane = threadIdx.x & 31;
    if (w >= N) return;
    int beg = g_off[w], end = g_off[w + 1];
    float ax = 0.f, ay = 0.f, az = 0.f, aw = 0.f;
    int e = beg;
    int col = lane * 4;
#pragma unroll 1
    for (; e + 4 <= end; e += 4) {
        int s0 = g_csrc[e], s1 = g_csrc[e + 1], s2 = g_csrc[e + 2], s3 = g_csrc[e + 3];
        uint2 u0 = *reinterpret_cast<const uint2*>(&g_t16[(size_t)s0 * D + col]);
        uint2 u1 = *reinterpret_cast<const uint2*>(&g_t16[(size_t)s1 * D + col]);
        uint2 u2 = *reinterpret_cast<const uint2*>(&g_t16[(size_t)s2 * D + col]);
        uint2 u3 = *reinterpret_cast<const uint2*>(&g_t16[(size_t)s3 * D + col]);
        float2 a, b;
        a = __half22float2(*(__half2*)&u0.x); b = __half22float2(*(__half2*)&u0.y);
        ax += a.x; ay += a.y; az += b.x; aw += b.y;
        a = __half22float2(*(__half2*)&u1.x); b = __half22float2(*(__half2*)&u1.y);
        ax += a.x; ay += a.y; az += b.x; aw += b.y;
        a = __half22float2(*(__half2*)&u2.x); b = __half22float2(*(__half2*)&u2.y);
        ax += a.x; ay += a.y; az += b.x; aw += b.y;
        a = __half22float2(*(__half2*)&u3.x); b = __half22float2(*(__half2*)&u3.y);
        ax += a.x; ay += a.y; az += b.x; aw += b.y;
    }
    for (; e < end; e++) {
        int s0 = g_csrc[e];
        uint2 u0 = *reinterpret_cast<const uint2*>(&g_t16[(size_t)s0 * D + col]);
        float2 a = __half22float2(*(__half2*)&u0.x);
        float2 b = __half22float2(*(__half2*)&u0.y);
        ax += a.x; ay += a.y; az += b.x; aw += b.y;
    }
    float inv = 1.0f / fmaxf((float)(end - beg), 1.0f);
    ax *= inv; ay *= inv; az *= inv; aw *= inv;
    float p = ax * ax + ay * ay + az * az + aw * aw;
#pragma unroll
    for (int off = 16; off; off >>= 1) p += __shfl_xor_sync(0xffffffffu, p, off);
    float s = chain_epl(sqrtf(p));
    float4 o = make_float4(ax * s, ay * s, az * s, aw * s);
    *reinterpret_cast<float4*>(&out[(size_t)w * D + col]) = o;
}

// ---------------- 2-term fp16-split tensor-core GEMM + hyperbolic epilogue --
// CTA: 128x128 output tile, K=128 resident. 16 warps, warp tile 32x32.
// ~105 KB smem + launch_bounds(512,2) -> 2 CTAs/SM: co-resident CTAs overlap
// prologue/epilogue with mainloop and smooth wave quantization.
// A split hi+lo (exact to 2^-22); W only hi. D = (Ahi+Alo)@Whi ~= A@Whi.
// mode 0: chain_epl, fp16 store (message tangents)
// mode 1: chain_ep,  fp32 store (final output)
// mode 2: chain_epl, fp32 store (inter-layer tangent)
#define STR 68   // half2-word row stride: 68 mod 32 == 4 -> banks 4g+c, conflict-free

__global__ __launch_bounds__(512, 2) void gemm_hyp_tc_kernel(
    const float* __restrict__ V, const float* __restrict__ W,
    const float* __restrict__ bias, float* __restrict__ out,
    __half* __restrict__ out16, int N, int mode)
{
    extern __shared__ uint32_t smem_u[];
    uint32_t* Ahi = smem_u;                 // [128][STR] half2 words
    uint32_t* Alo = Ahi + 128 * STR;
    uint32_t* Whi = Alo + 128 * STR;
    float* bias_s = (float*)(Whi + 128 * STR);  // [128]
    float* red    = bias_s + 128;               // [128][4]
    float* scl    = red + 512;                  // [128]

    int tid  = threadIdx.x;
    int lane = tid & 31;
    int warp = tid >> 5;
    int rbase = (warp >> 2) * 32;   // 4 row groups
    int cbase = (warp & 3) * 32;    // 4 col groups
    int m0 = blockIdx.x * 128;

    if (tid < 128) bias_s[tid] = bias[tid];

    // ---- load tiles; A split hi/lo, W hi only ----
#pragma unroll
    for (int i = 0; i < 8; i++) {
        int idx = tid + i * 512;            // 4096 float4 slots
        int row = idx >> 5;
        int c4  = (idx & 31) * 4;           // float col, multiple of 4
        int wofs = row * STR + (c4 >> 1);   // half2-word offset

        float4 av = make_float4(0.f, 0.f, 0.f, 0.f);
        int gm = m0 + row;
        if (gm < N) av = *reinterpret_cast<const float4*>(&V[(size_t)gm * D + c4]);
        uint32_t h0, l0, h1, l1;
        split2(av.x, av.y, h0, l0);
        split2(av.z, av.w, h1, l1);
        Ahi[wofs] = h0; Ahi[wofs + 1] = h1;
        Alo[wofs] = l0; Alo[wofs + 1] = l1;

        float4 wv = *reinterpret_cast<const float4*>(&W[(size_t)row * D + c4]);
        __half2 wh0 = __floats2half2_rn(wv.x, wv.y);
        __half2 wh1 = __floats2half2_rn(wv.z, wv.w);
        Whi[wofs]     = *reinterpret_cast<uint32_t*>(&wh0);
        Whi[wofs + 1] = *reinterpret_cast<uint32_t*>(&wh1);
    }
    __syncthreads();

    float acc[2][4][4];
#pragma unroll
    for (int rt = 0; rt < 2; rt++)
#pragma unroll
        for (int ct = 0; ct < 4; ct++)
#pragma unroll
            for (int q = 0; q < 4; q++) acc[rt][ct][q] = 0.0f;

    int c = lane & 3;
    int g = lane >> 2;

#pragma unroll
    for (int ks = 0; ks < 8; ks++) {
        int k0 = ks * 8;                    // word offset of this k16 step
        uint32_t ah[2][4], al[2][4];
#pragma unroll
        for (int rt = 0; rt < 2; rt++) {
            int r0 = rbase + rt * 16 + g;
            int b0 = r0 * STR + k0 + c;
            int b1 = (r0 + 8) * STR + k0 + c;
            ah[rt][0] = Ahi[b0];     ah[rt][1] = Ahi[b1];
            ah[rt][2] = Ahi[b0 + 4]; ah[rt][3] = Ahi[b1 + 4];
            al[rt][0] = Alo[b0];     al[rt][1] = Alo[b1];
            al[rt][2] = Alo[b0 + 4]; al[rt][3] = Alo[b1 + 4];
        }
#pragma unroll
        for (int ct = 0; ct < 4; ct++) {
            int col = cbase + ct * 8 + g;
            int wb = col * STR + k0 + c;
            uint32_t bh0 = Whi[wb], bh1 = Whi[wb + 4];
#pragma unroll
            for (int rt = 0; rt < 2; rt++) {
                mma_f16(acc[rt][ct], ah[rt][0], ah[rt][1], ah[rt][2], ah[rt][3], bh0, bh1);
                mma_f16(acc[rt][ct], al[rt][0], al[rt][1], al[rt][2], al[rt][3], bh0, bh1);
            }
        }
    }

    // ---- epilogue: bias add + per-row sumsq ----
    float prow[2][2];
#pragma unroll
    for (int rt = 0; rt < 2; rt++) {
        prow[rt][0] = 0.f; prow[rt][1] = 0.f;
#pragma unroll
        for (int ct = 0; ct < 4; ct++) {
            int colb = cbase + ct * 8 + 2 * c;
            float u0 = acc[rt][ct][0] + bias_s[colb];
            float u1 = acc[rt][ct][1] + bias_s[colb + 1];
            float u2 = acc[rt][ct][2] + bias_s[colb];
            float u3 = acc[rt][ct][3] + bias_s[colb + 1];
            acc[rt][ct][0] = u0; acc[rt][ct][1] = u1;
            acc[rt][ct][2] = u2; acc[rt][ct][3] = u3;
            prow[rt][0] += u0 * u0 + u1 * u1;
            prow[rt][1] += u2 * u2 + u3 * u3;
        }
#pragma unroll
        for (int o = 1; o < 4; o <<= 1) {
            prow[rt][0] += __shfl_xor_sync(0xffffffffu, prow[rt][0], o);
            prow[rt][1] += __shfl_xor_sync(0xffffffffu, prow[rt][1], o);
        }
    }
    int cg = warp & 3;
    if (c == 0) {
#pragma unroll
        for (int rt = 0; rt < 2; rt++) {
            int r0 = rbase + rt * 16 + g;
            red[r0 * 4 + cg]       = prow[rt][0];
            red[(r0 + 8) * 4 + cg] = prow[rt][1];
        }
    }
    __syncthreads();
    if (tid < 128) {
        float s = red[tid * 4] + red[tid * 4 + 1] + red[tid * 4 + 2] + red[tid * 4 + 3];
        float n = sqrtf(s);
        scl[tid] = (mode == 1) ? chain_ep(n) : chain_epl(n);
    }
    __syncthreads();

    // ---- scaled store ----
#pragma unroll
    for (int rt = 0; rt < 2; rt++) {
        int r0 = rbase + rt * 16 + g;
        float s0 = scl[r0];
        float s1 = scl[r0 + 8];
        int gm0 = m0 + r0;
        int gm1 = gm0 + 8;
#pragma unroll
        for (int ct = 0; ct < 4; ct++) {
            int colb = cbase + ct * 8 + 2 * c;
            if (mode == 0) {
                if (gm0 < N) {
                    __half2 hv = __floats2half2_rn(acc[rt][ct][0] * s0, acc[rt][ct][1] * s0);
                    *reinterpret_cast<__half2*>(&out16[(size_t)gm0 * D + colb]) = hv;
                }
                if (gm1 < N) {
                    __half2 hv = __floats2half2_rn(acc[rt][ct][2] * s1, acc[rt][ct][3] * s1);
                    *reinterpret_cast<__half2*>(&out16[(size_t)gm1 * D + colb]) = hv;
                }
            } else {
                if (gm0 < N) {
                    float2 o = make_float2(acc[rt][ct][0] * s0, acc[rt][ct][1] * s0);
                    *reinterpret_cast<float2*>(&out[(size_t)gm0 * D + colb]) = o;
                }
                if (gm1 < N) {
                    float2 o = make_float2(acc[rt][ct][2] * s1, acc[rt][ct][3] * s1);
                    *reinterpret_cast<float2*>(&out[(size_t)gm1 * D + colb]) = o;
                }
            }
        }
    }
}

// ---------------- host ------------------------------------------------------
extern "C" void kernel_launch(void* const* d_in, const int* in_sizes, int n_in,
                              void* d_out, int out_size)
{
    const float* x     = (const float*)d_in[0];
    const int*   ei    = (const int*)d_in[1];
    const float* msg_W = (const float*)d_in[2];
    const float* msg_b = (const float*)d_in[3];
    const float* upd_W = (const float*)d_in[4];
    const float* upd_b = (const float*)d_in[5];
    float* outp = (float*)d_out;

    int N = in_sizes[0] / D;
    int E = in_sizes[1] / 2;
    int L = in_sizes[3] / D;
    if (N > MAXN || E > MAXE) return;

    const int* src = ei;
    const int* dst = ei + E;

    float *p_v, *p_h;
    __half* p_t16;
    int *p_deg;
    cudaGetSymbolAddress((void**)&p_v,   g_v);
    cudaGetSymbolAddress((void**)&p_t16, g_t16);
    cudaGetSymbolAddress((void**)&p_h,   g_h);
    cudaGetSymbolAddress((void**)&p_deg, g_deg);

    const int SMEM = (3 * 128 * STR + 128 + 512 + 128) * (int)sizeof(uint32_t);
    static bool init_done = false;
    static cudaStream_t s1;
    static cudaEvent_t ev_fork, ev_join;
    if (!init_done) {
        cudaFuncSetAttribute(gemm_hyp_tc_kernel,
                             cudaFuncAttributeMaxDynamicSharedMemorySize, SMEM);
        cudaStreamCreateWithFlags(&s1, cudaStreamNonBlocking);
        cudaEventCreateWithFlags(&ev_fork, cudaEventDisableTiming);
        cudaEventCreateWithFlags(&ev_join, cudaEventDisableTiming);
        init_done = true;
    }

    cudaStream_t s0 = 0;

    // ---- fork: CSR build on side stream ----
    cudaEventRecord(ev_fork, s0);
    cudaStreamWaitEvent(s1, ev_fork, 0);
    zero_int_kernel<<<(N + 255) / 256, 256, 0, s1>>>(p_deg, N);
    hist_kernel<<<(E + 255) / 256, 256, 0, s1>>>(dst, E);
    scan_kernel<<<1, 1024, 0, s1>>>(N);
    fill_kernel<<<(E + 255) / 256, 256, 0, s1>>>(src, dst, E);
    cudaEventRecord(ev_join, s1);

    int gemm_blocks  = (N + 127) / 128;
    int warp_blocksN = (N * 32 + 255) / 256;

    prep_log0_kernel<<<warp_blocksN, 256>>>(x, p_v, N);

    bool joined = false;
    const float* v_in = p_v;
    for (int l = 0; l < L; l++) {
        gemm_hyp_tc_kernel<<<gemm_blocks, 512, SMEM>>>(v_in, msg_W + (size_t)l * D * D,
                                                       msg_b + (size_t)l * D,
                                                       nullptr, p_t16, N, 0);
        if (!joined) { cudaStreamWaitEvent(s0, ev_join, 0); joined = true; }
        agg_kernel<<<warp_blocksN, 256>>>(p_v, N);
        if (l == L - 1) {
            gemm_hyp_tc_kernel<<<gemm_blocks, 512, SMEM>>>(p_v, upd_W + (size_t)l * D * D,
                                                           upd_b + (size_t)l * D,
                                                           outp, nullptr, N, 1);
        } else {
            gemm_hyp_tc_kernel<<<gemm_blocks, 512, SMEM>>>(p_v, upd_W + (size_t)l * D * D,
                                                           upd_b + (size_t)l * D,
                                                           p_h, nullptr, N, 2);
            v_in = p_h;
        }
    }
}